// round 13
// baseline (speedup 1.0000x reference)
#include <cuda_runtime.h>
#include <cuda_fp16.h>
#include <math.h>

#define NTOK 2304
#define HWDIM 48
#define FEATC 256
#define NKT 36
#define NQT 18

typedef unsigned long long ull;
typedef unsigned int u32;

__device__ float g_scratch[17763840];
__device__ float g_scale[256];
__device__ float g_shift[256];

__device__ __forceinline__ u32 f16pack(float lo, float hi) {
    u32 r;
    asm("cvt.rn.f16x2.f32 %0, %1, %2;" : "=r"(r) : "f"(hi), "f"(lo));
    return r;
}
__device__ __forceinline__ u32 ex2h2(u32 x) {
    u32 r;
    asm("ex2.approx.f16x2 %0, %1;" : "=r"(r) : "r"(x));
    return r;
}
__device__ __forceinline__ void mma16816(float* d, u32 a0, u32 a1, u32 a2, u32 a3,
                                         u32 b0, u32 b1) {
    asm volatile(
        "mma.sync.aligned.m16n8k16.row.col.f32.f16.f16.f32 "
        "{%0,%1,%2,%3},{%4,%5,%6,%7},{%8,%9},{%0,%1,%2,%3};"
        : "+f"(d[0]), "+f"(d[1]), "+f"(d[2]), "+f"(d[3])
        : "r"(a0), "r"(a1), "r"(a2), "r"(a3), "r"(b0), "r"(b1));
}
__device__ __forceinline__ u32 smem_u32(const void* p) {
    u32 a;
    asm("{ .reg .u64 t; cvta.to.shared.u64 t, %1; cvt.u32.u64 %0, t; }" : "=r"(a) : "l"(p));
    return a;
}
__device__ __forceinline__ void ldsm4(u32* r, u32 addr) {
    asm volatile("ldmatrix.sync.aligned.m8n8.x4.shared.b16 {%0,%1,%2,%3}, [%4];"
                 : "=r"(r[0]), "=r"(r[1]), "=r"(r[2]), "=r"(r[3]) : "r"(addr));
}
__device__ __forceinline__ void ldsm2(u32* r, u32 addr) {
    asm volatile("ldmatrix.sync.aligned.m8n8.x2.shared.b16 {%0,%1}, [%2];"
                 : "=r"(r[0]), "=r"(r[1]) : "r"(addr));
}
#define CP16(dst, src) asm volatile("cp.async.ca.shared.global [%0], [%1], 16;" :: "r"(dst), "l"(src))
#define CP_COMMIT()    asm volatile("cp.async.commit_group;" ::: "memory")
#define CP_WAIT0()     asm volatile("cp.async.wait_group 0;" ::: "memory")
#define CP_WAIT1()     asm volatile("cp.async.wait_group 1;" ::: "memory")

// ================= PE -> fp16 channels appended to XIN q/k slices =================
__global__ void pe16_kernel(__half* __restrict__ XIN) {
    int idx = blockIdx.x * 256 + threadIdx.x;
    if (idx >= 32 * NTOK) return;
    int tok = idx >> 5, c = idx & 31;
    float val = 0.f;
    if (c < 30) {
        int i = tok / HWDIM, j = tok % HWDIM;
        const float SC = 6.283185307179586f;
        int axis = c / 10, t = c % 10;
        float e;
        if (axis == 0)      e = (float)(i + 1) / (HWDIM + 1e-6f) * SC;
        else if (axis == 1) e = (float)(j + 1) / (HWDIM + 1e-6f) * SC;
        else                e = SC;
        float freq = powf(10000.0f, (2.0f * (float)(t >> 1)) / 10.0f);
        float ph = e / freq;
        val = (t & 1) ? cosf(ph) : sinf(ph);
    }
    __half h = __float2half_rn(val);
#pragma unroll
    for (int s = 0; s < 8; s++)
        XIN[(size_t)s * 663552 + (size_t)tok * 288 + 256 + c] = h;
}

// ================= weight conversion =================
__global__ void wconv_kernel(const float* __restrict__ wq, const float* __restrict__ wk,
                             const float* __restrict__ wv, const float* __restrict__ wfc,
                             const float* __restrict__ w1, const float* __restrict__ w2,
                             __half* __restrict__ W16) {
    int idx = blockIdx.x * 256 + threadIdx.x;
    if (idx >= 409600) return;
    float v;
    if (idx < 147456) {
        int w = idx / 73728;
        int rem = idx - w * 73728;
        int r = rem / 288, c = rem - r * 288;
        const float* src = w ? wk : wq;
        v = (c < 286) ? src[(size_t)r * 286 + c] : 0.f;
    } else {
        int idx2 = idx - 147456;
        int w = idx2 >> 16, r = (idx2 >> 8) & 255, c = idx2 & 255;
        const float* src = (w == 0) ? wv : (w == 1) ? wfc : (w == 2) ? w1 : w2;
        v = src[(size_t)r * 256 + c];
    }
    W16[idx] = __float2half_rn(v);
}

// ================= input transpose+convert =================
__global__ void __launch_bounds__(256) xconv_kernel(const float* __restrict__ q,
                                                    const float* __restrict__ k,
                                                    const float* __restrict__ v,
                                                    __half* __restrict__ XIN) {
    __shared__ float tile[32][132];
    int z = blockIdx.z;
    int op = z >> 2, b = z & 3;
    const float* src = (op == 0 ? q : op == 1 ? k : v) + (size_t)b * FEATC * NTOK;
    int ldx = (op == 2) ? 256 : 288;
    __half* dst = XIN + (op == 2 ? (size_t)8 * 663552 + (size_t)b * 589824
                                 : (size_t)(op * 4 + b) * 663552);
    int t0 = blockIdx.x * 128, c0 = blockIdx.y * 32;
    int tid = threadIdx.x;
#pragma unroll
    for (int j = 0; j < 4; j++) {
        int i = tid + j * 256;
        int row = i >> 5, f4 = i & 31;
        float4 vv = *(const float4*)(src + (size_t)(c0 + row) * NTOK + t0 + f4 * 4);
        tile[row][f4 * 4] = vv.x;
        tile[row][f4 * 4 + 1] = vv.y;
        tile[row][f4 * 4 + 2] = vv.z;
        tile[row][f4 * 4 + 3] = vv.w;
    }
    __syncthreads();
#pragma unroll
    for (int j = 0; j < 2; j++) {
        int i = tid + j * 256;
        int tok = i >> 2, q4 = i & 3;
        u32 out4[4];
#pragma unroll
        for (int p = 0; p < 4; p++) {
            int c = q4 * 8 + p * 2;
            out4[p] = f16pack(tile[c][tok], tile[c + 1][tok]);
        }
        *(uint4*)(dst + (size_t)(t0 + tok) * ldx + c0 + q4 * 8) = *(uint4*)out4;
    }
}

// ================= HMMA GEMM body: 4 warps, 64oc x 128tok, 3-stage cp.async, 1 sync/iter ==========
// stage i: W tile (64 x 32) at i*15360 (pitch 80), X tile (128 x 32) at i*15360+5120 (pitch 80)
__device__ __forceinline__ void hgemm_body(const __half* __restrict__ W16, int kdim,
                                           const __half* __restrict__ XH, int ldx,
                                           const float* __restrict__ bVec,
                                           const float* __restrict__ resid,
                                           float qscale, int relu,
                                           float* __restrict__ outF,
                                           __half* __restrict__ outTok,
                                           __half* __restrict__ outC,
                                           unsigned char* smem) {
    int tid = threadIdx.x, wid = tid >> 5, lane = tid & 31;
    int wc = wid;                       // warp covers tok [wc*32, wc*32+32)
    int oc0 = blockIdx.y * 64, t0 = blockIdx.x * 128;
    u32 sbase = smem_u32(smem);
    int nsteps = kdim >> 5;

    float acc[4][4][4];
#pragma unroll
    for (int m = 0; m < 4; m++)
#pragma unroll
        for (int n = 0; n < 4; n++)
#pragma unroll
            for (int c = 0; c < 4; c++) acc[m][n][c] = 0.f;

    // prologue: stages 0,1
#pragma unroll
    for (int ps = 0; ps < 2; ps++) {
        u32 sb = sbase + ps * 15360;
        int kk = ps << 5;
#pragma unroll
        for (int i = 0; i < 2; i++) {
            int idx = tid + i * 128;
            int row = idx >> 2, ch = idx & 3;
            CP16(sb + row * 80 + ch * 16, W16 + (size_t)(oc0 + row) * kdim + kk + ch * 8);
        }
#pragma unroll
        for (int i = 0; i < 4; i++) {
            int idx = tid + i * 128;
            int row = idx >> 2, ch = idx & 3;
            CP16(sb + 5120 + row * 80 + ch * 16, XH + (size_t)(t0 + row) * ldx + kk + ch * 8);
        }
        CP_COMMIT();
    }

    for (int s = 0; s < nsteps; s++) {
        if (s == nsteps - 1) { CP_WAIT0(); } else { CP_WAIT1(); }
        __syncthreads();
        if (s + 2 < nsteps) {
            int kk = (s + 2) << 5;
            u32 sb = sbase + ((s + 2) % 3) * 15360;
#pragma unroll
            for (int i = 0; i < 2; i++) {
                int idx = tid + i * 128;
                int row = idx >> 2, ch = idx & 3;
                CP16(sb + row * 80 + ch * 16, W16 + (size_t)(oc0 + row) * kdim + kk + ch * 8);
            }
#pragma unroll
            for (int i = 0; i < 4; i++) {
                int idx = tid + i * 128;
                int row = idx >> 2, ch = idx & 3;
                CP16(sb + 5120 + row * 80 + ch * 16, XH + (size_t)(t0 + row) * ldx + kk + ch * 8);
            }
            CP_COMMIT();
        }
        u32 sWst = sbase + (s % 3) * 15360;
        u32 sXst = sWst + 5120;
#pragma unroll
        for (int ks = 0; ks < 2; ks++) {
            int cb0 = ks * 16;
            u32 a[4][4], bfr[4][2];
#pragma unroll
            for (int m = 0; m < 4; m++) {
                int row = m * 16 + (lane & 15);
                int col = cb0 + (lane >> 4) * 8;
                ldsm4(a[m], sWst + row * 80 + col * 2);
            }
#pragma unroll
            for (int p = 0; p < 2; p++) {
                u32 t[4];
                int row = wc * 32 + p * 16 + ((lane >> 4) & 1) * 8 + (lane & 7);
                int col = cb0 + ((lane >> 3) & 1) * 8;
                ldsm4(t, sXst + row * 80 + col * 2);
                bfr[2 * p][0] = t[0]; bfr[2 * p][1] = t[1];
                bfr[2 * p + 1][0] = t[2]; bfr[2 * p + 1][1] = t[3];
            }
#pragma unroll
            for (int m = 0; m < 4; m++)
#pragma unroll
                for (int n = 0; n < 4; n++)
                    mma16816(acc[m][n], a[m][0], a[m][1], a[m][2], a[m][3], bfr[n][0], bfr[n][1]);
        }
    }

#pragma unroll
    for (int m = 0; m < 4; m++) {
#pragma unroll
        for (int n = 0; n < 4; n++) {
            int r0 = oc0 + m * 16 + (lane >> 2);
            int r1 = r0 + 8;
            int cX = t0 + wc * 32 + n * 8 + (lane & 3) * 2;
            float v00 = acc[m][n][0], v01 = acc[m][n][1];
            float v10 = acc[m][n][2], v11 = acc[m][n][3];
            if (bVec) {
                float bv0 = bVec[r0], bv1 = bVec[r1];
                v00 += bv0; v01 += bv0; v10 += bv1; v11 += bv1;
            }
            if (relu) {
                v00 = fmaxf(v00, 0.f); v01 = fmaxf(v01, 0.f);
                v10 = fmaxf(v10, 0.f); v11 = fmaxf(v11, 0.f);
            }
            if (resid) {
                v00 += resid[(size_t)r0 * NTOK + cX];
                v01 += resid[(size_t)r0 * NTOK + cX + 1];
                v10 += resid[(size_t)r1 * NTOK + cX];
                v11 += resid[(size_t)r1 * NTOK + cX + 1];
            }
            v00 *= qscale; v01 *= qscale; v10 *= qscale; v11 *= qscale;
            acc[m][n][0] = v00; acc[m][n][1] = v01; acc[m][n][2] = v10; acc[m][n][3] = v11;
            if (outF) {
                *(float2*)(outF + (size_t)r0 * NTOK + cX) = make_float2(v00, v01);
                *(float2*)(outF + (size_t)r1 * NTOK + cX) = make_float2(v10, v11);
            }
            if (outC) {
                *(u32*)(outC + (size_t)r0 * NTOK + cX) = f16pack(v00, v01);
                *(u32*)(outC + (size_t)r1 * NTOK + cX) = f16pack(v10, v11);
            }
        }
    }
    if (outTok) {
        __half (*sT)[72] = (__half(*)[72])smem;   // [128 tok][72]
        __syncthreads();
#pragma unroll
        for (int m = 0; m < 4; m++)
#pragma unroll
            for (int n = 0; n < 4; n++) {
                int lr0 = m * 16 + (lane >> 2);
                int lc = wc * 32 + n * 8 + (lane & 3) * 2;
                sT[lc][lr0]     = __float2half_rn(acc[m][n][0]);
                sT[lc + 1][lr0] = __float2half_rn(acc[m][n][1]);
                sT[lc][lr0 + 8]     = __float2half_rn(acc[m][n][2]);
                sT[lc + 1][lr0 + 8] = __float2half_rn(acc[m][n][3]);
            }
        __syncthreads();
#pragma unroll
        for (int i = 0; i < 8; i++) {
            int idx = tid + i * 128;
            int row = idx >> 3, ch = idx & 7;
            *(uint4*)(outTok + (size_t)(t0 + row) * 256 + oc0 + ch * 8) =
                *(uint4*)&sT[row][ch * 8];
        }
    }
}

// proj: z = op*4 + b
__global__ void __launch_bounds__(128) proj_h_kernel(const __half* __restrict__ W16,
                                                     const __half* __restrict__ XIN,
                                                     __half* __restrict__ QH,
                                                     __half* __restrict__ KH,
                                                     __half* __restrict__ VH) {
    __shared__ __align__(16) unsigned char smem[46080];
    int z = blockIdx.z;
    int op = z >> 2, b = z & 3;
    if (op == 0) {
        hgemm_body(W16, 288, XIN + (size_t)b * 663552, 288, nullptr, nullptr,
                   0.2550348634f, 0, nullptr, QH + (size_t)b * 589824, nullptr, smem);
    } else if (op == 1) {
        hgemm_body(W16 + 73728, 288, XIN + (size_t)(4 + b) * 663552, 288, nullptr, nullptr,
                   1.0f, 0, nullptr, KH + (size_t)b * 589824, nullptr, smem);
    } else {
        hgemm_body(W16 + 147456, 256, XIN + (size_t)8 * 663552 + (size_t)b * 589824, 256,
                   nullptr, nullptr, 1.0f, 0, nullptr, nullptr, VH + (size_t)b * 589824, smem);
    }
}

__global__ void __launch_bounds__(128) hgemm_kernel(const __half* __restrict__ W16,
                                                    const __half* __restrict__ XH,
                                                    const float* __restrict__ bVec,
                                                    const float* __restrict__ resid,
                                                    float* __restrict__ outF,
                                                    __half* __restrict__ outTok,
                                                    int relu) {
    __shared__ __align__(16) unsigned char smem[46080];
    size_t off = (size_t)blockIdx.z * 589824;
    hgemm_body(W16, 256, XH + off, 256, bVec, resid ? resid + off : nullptr, 1.0f, relu,
               outF ? outF + off : nullptr, outTok ? outTok + off : nullptr, nullptr, smem);
}

// ================= warp-MMA flash attention: 3-stage cp.async, 1 sync/iter =================
// stage i: K (64x32, pitch 80) at sKV + i*10880 ; V (40x72, pitch 144) at +5120
__global__ void __launch_bounds__(128) attn_mma_kernel(const __half* __restrict__ QH,
                                                       const __half* __restrict__ KH,
                                                       const __half* __restrict__ VH,
                                                       __half* __restrict__ OH) {
    __shared__ __half sQ[128][40];
    __shared__ __align__(16) unsigned char sKV[32640];

    int tid = threadIdx.x, wid = tid >> 5, lane = tid & 31;
    int q0 = blockIdx.x * 128;
    int bh = blockIdx.y;
    int b = bh >> 3, h = bh & 7;
    u32 sQa = smem_u32(&sQ[0][0]);
    u32 sKVa = smem_u32(sKV);

#pragma unroll
    for (int c = 0; c < 4; c++) {
        int i = tid + c * 128;
        int row = i >> 2, ch = i & 3;
        *(uint4*)&sQ[row][ch * 8] =
            *(const uint4*)(QH + ((size_t)b * NTOK + q0 + row) * 256 + h * 32 + ch * 8);
    }
    // V static rows for all 3 stages: row 32 = ones, rows 33-39 = zero
#pragma unroll
    for (int st = 0; st < 3; st++) {
        u32* v32 = (u32*)(sKV + st * 10880 + 5120 + 32 * 144);
        if (tid < 32) v32[tid] = 0x3C003C00u;
        u32* v33 = (u32*)(sKV + st * 10880 + 5120 + 33 * 144);
        for (int i = tid; i < 252; i += 128) v33[i] = 0u;
    }
    // prologue: stages 0,1
#pragma unroll
    for (int ps = 0; ps < 2; ps++) {
        int kb = ps * 64;
        u32 sb = sKVa + ps * 10880;
#pragma unroll
        for (int i = 0; i < 2; i++) {
            int idx = tid + i * 128;
            int row = idx >> 2, ch = idx & 3;
            CP16(sb + row * 80 + ch * 16,
                 KH + ((size_t)b * NTOK + kb + row) * 256 + h * 32 + ch * 8);
        }
#pragma unroll
        for (int i = 0; i < 2; i++) {
            int idx = tid + i * 128;
            int row = idx >> 3, ch = idx & 7;
            CP16(sb + 5120 + row * 144 + ch * 16,
                 VH + ((size_t)(b * 256 + h * 32 + row)) * NTOK + kb + ch * 8);
        }
        CP_COMMIT();
    }
    __syncthreads();

    u32 qa[2][2][4];
#pragma unroll
    for (int m = 0; m < 2; m++)
#pragma unroll
        for (int ks = 0; ks < 2; ks++) {
            int row = wid * 32 + m * 16 + (lane & 15);
            int col = ks * 16 + (lane >> 4) * 8;
            ldsm4(qa[m][ks], sQa + row * 80 + col * 2);
        }

    float Oa[2][5][4];
#pragma unroll
    for (int m = 0; m < 2; m++)
#pragma unroll
        for (int n = 0; n < 5; n++)
#pragma unroll
            for (int c = 0; c < 4; c++) Oa[m][n][c] = 0.f;

#pragma unroll 1
    for (int kt = 0; kt < NKT; kt++) {
        if (kt == NKT - 1) { CP_WAIT0(); } else { CP_WAIT1(); }
        __syncthreads();
        if (kt + 2 < NKT) {
            int kb = (kt + 2) * 64;
            u32 sb = sKVa + ((kt + 2) % 3) * 10880;
#pragma unroll
            for (int i = 0; i < 2; i++) {
                int idx = tid + i * 128;
                int row = idx >> 2, ch = idx & 3;
                CP16(sb + row * 80 + ch * 16,
                     KH + ((size_t)b * NTOK + kb + row) * 256 + h * 32 + ch * 8);
            }
#pragma unroll
            for (int i = 0; i < 2; i++) {
                int idx = tid + i * 128;
                int row = idx >> 3, ch = idx & 7;
                CP16(sb + 5120 + row * 144 + ch * 16,
                     VH + ((size_t)(b * 256 + h * 32 + row)) * NTOK + kb + ch * 8);
            }
            CP_COMMIT();
        }
        u32 sKst = sKVa + (kt % 3) * 10880;
        u32 sVst = sKst + 5120;

        float S[2][8][4];
#pragma unroll
        for (int m = 0; m < 2; m++)
#pragma unroll
            for (int n = 0; n < 8; n++)
#pragma unroll
                for (int c = 0; c < 4; c++) S[m][n][c] = 0.f;

#pragma unroll
        for (int ks = 0; ks < 2; ks++) {
            int cb0 = ks * 16;
#pragma unroll
            for (int p = 0; p < 4; p++) {
                u32 t[4];
                int row = p * 16 + ((lane >> 4) & 1) * 8 + (lane & 7);
                int col = cb0 + ((lane >> 3) & 1) * 8;
                ldsm4(t, sKst + row * 80 + col * 2);
                mma16816(S[0][2 * p],     qa[0][ks][0], qa[0][ks][1], qa[0][ks][2], qa[0][ks][3], t[0], t[1]);
                mma16816(S[1][2 * p],     qa[1][ks][0], qa[1][ks][1], qa[1][ks][2], qa[1][ks][3], t[0], t[1]);
                mma16816(S[0][2 * p + 1], qa[0][ks][0], qa[0][ks][1], qa[0][ks][2], qa[0][ks][3], t[2], t[3]);
                mma16816(S[1][2 * p + 1], qa[1][ks][0], qa[1][ks][1], qa[1][ks][2], qa[1][ks][3], t[2], t[3]);
            }
        }

        u32 P[2][8][2];
#pragma unroll
        for (int m = 0; m < 2; m++)
#pragma unroll
            for (int nb = 0; nb < 8; nb++) {
                P[m][nb][0] = ex2h2(f16pack(S[m][nb][0], S[m][nb][1]));
                P[m][nb][1] = ex2h2(f16pack(S[m][nb][2], S[m][nb][3]));
            }

#pragma unroll
        for (int ks = 0; ks < 4; ks++) {
            int cb0 = ks * 16;
#pragma unroll
            for (int p = 0; p < 2; p++) {
                u32 t[4];
                int row = p * 16 + ((lane >> 4) & 1) * 8 + (lane & 7);
                int col = cb0 + ((lane >> 3) & 1) * 8;
                ldsm4(t, sVst + row * 144 + col * 2);
#pragma unroll
                for (int m = 0; m < 2; m++) {
                    mma16816(Oa[m][2 * p],     P[m][2 * ks][0], P[m][2 * ks][1],
                             P[m][2 * ks + 1][0], P[m][2 * ks + 1][1], t[0], t[1]);
                    mma16816(Oa[m][2 * p + 1], P[m][2 * ks][0], P[m][2 * ks][1],
                             P[m][2 * ks + 1][0], P[m][2 * ks + 1][1], t[2], t[3]);
                }
            }
            {
                u32 t2[2];
                int row = 32 + (lane & 7);
                int col = cb0 + ((lane >> 3) & 1) * 8;
                ldsm2(t2, sVst + row * 144 + col * 2);
#pragma unroll
                for (int m = 0; m < 2; m++)
                    mma16816(Oa[m][4], P[m][2 * ks][0], P[m][2 * ks][1],
                             P[m][2 * ks + 1][0], P[m][2 * ks + 1][1], t2[0], t2[1]);
            }
        }
    }

    int qb = q0 + wid * 32;
#pragma unroll
    for (int m = 0; m < 2; m++) {
        float li0 = 1.f / __shfl_sync(0xffffffffu, Oa[m][4][0], lane & ~3);
        float li1 = 1.f / __shfl_sync(0xffffffffu, Oa[m][4][2], lane & ~3);
        int r0 = qb + m * 16 + (lane >> 2);
#pragma unroll
        for (int nb = 0; nb < 4; nb++) {
            int d = nb * 8 + (lane & 3) * 2;
            *(u32*)(OH + ((size_t)b * NTOK + r0) * 256 + h * 32 + d) =
                f16pack(Oa[m][nb][0] * li0, Oa[m][nb][1] * li0);
            *(u32*)(OH + ((size_t)b * NTOK + r0 + 8) * 256 + h * 32 + d) =
                f16pack(Oa[m][nb][2] * li1, Oa[m][nb][3] * li1);
        }
    }
}

// ================= BN =================
__global__ void bnstats_kernel(const float* __restrict__ pre,
                               const float* __restrict__ gamma,
                               const float* __restrict__ beta) {
    int c = blockIdx.x;
    float s = 0.f, s2 = 0.f;
    for (int b = 0; b < 4; b++) {
        const float* p = pre + ((size_t)b * FEATC + c) * NTOK;
        for (int i = threadIdx.x; i < NTOK / 4; i += 256) {
            float4 v = ((const float4*)p)[i];
            s += v.x + v.y + v.z + v.w;
            s2 += v.x * v.x + v.y * v.y + v.z * v.z + v.w * v.w;
        }
    }
    __shared__ float sh0[256], sh1[256];
    sh0[threadIdx.x] = s;
    sh1[threadIdx.x] = s2;
    __syncthreads();
    for (int st = 128; st > 0; st >>= 1) {
        if (threadIdx.x < st) {
            sh0[threadIdx.x] += sh0[threadIdx.x + st];
            sh1[threadIdx.x] += sh1[threadIdx.x + st];
        }
        __syncthreads();
    }
    if (threadIdx.x == 0) {
        const float n = 4.0f * NTOK;
        float mean = sh0[0] / n;
        float var = sh1[0] / n - mean * mean;
        float is = rsqrtf(var + 1e-5f);
        float scl = gamma[c] * is;
        g_scale[c] = scl;
        g_shift[c] = beta[c] - mean * scl;
    }
}

__global__ void bnapply_kernel(const float* __restrict__ pre, float* __restrict__ out) {
    int idx = blockIdx.x * 256 + threadIdx.x;
    if (idx >= 589824) return;
    int c = ((idx << 2) / NTOK) & 255;
    float sc = g_scale[c], sh = g_shift[c];
    float4 v = ((const float4*)pre)[idx];
    v.x = v.x * sc + sh; v.y = v.y * sc + sh;
    v.z = v.z * sc + sh; v.w = v.w * sc + sh;
    ((float4*)out)[idx] = v;
}

// ================= launch =================
extern "C" void kernel_launch(void* const* d_in, const int* in_sizes, int n_in,
                              void* d_out, int out_size) {
    const float* q     = (const float*)d_in[0];
    const float* k     = (const float*)d_in[1];
    const float* v     = (const float*)d_in[2];
    const float* wq    = (const float*)d_in[3];
    const float* wk    = (const float*)d_in[4];
    const float* wv    = (const float*)d_in[5];
    const float* wfc   = (const float*)d_in[6];
    const float* w1    = (const float*)d_in[7];
    const float* b1    = (const float*)d_in[8];
    const float* w2    = (const float*)d_in[9];
    const float* b2    = (const float*)d_in[10];
    const float* gamma = (const float*)d_in[11];
    const float* beta  = (const float*)d_in[12];
    float* out = (float*)d_out;

    float* base = nullptr;
    cudaGetSymbolAddress((void**)&base, g_scratch);
    float* O2  = base;
    float* PRE = base + 2359296;
    __half* hb  = (__half*)(base + 4718592);
    __half* W16 = hb;
    __half* XIN = hb + 409600;
    __half* QH  = hb + 8077312;
    __half* KH  = QH + 2359296;
    __half* VH  = KH + 2359296;
    __half* OH  = VH + 2359296;
    __half* O2h = OH + 2359296;
    __half* H1h = O2h + 2359296;

    pe16_kernel<<<(32 * NTOK + 255) / 256, 256>>>(XIN);
    wconv_kernel<<<1600, 256>>>(wq, wk, wv, wfc, w1, w2, W16);
    {
        dim3 g(NTOK / 128, FEATC / 32, 12);
        xconv_kernel<<<g, 256>>>(q, k, v, XIN);
    }
    {
        dim3 g(NTOK / 128, 4, 12);
        proj_h_kernel<<<g, 128>>>(W16, XIN, QH, KH, VH);
    }
    {
        dim3 ga(NQT, 32);
        attn_mma_kernel<<<ga, 128>>>(QH, KH, VH, OH);
    }
    {
        dim3 g(NTOK / 128, 4, 4);
        hgemm_kernel<<<g, 128>>>(W16 + 212992, OH, nullptr, nullptr, O2, O2h, 0);
        hgemm_kernel<<<g, 128>>>(W16 + 278528, O2h, b1, nullptr, nullptr, H1h, 1);
        hgemm_kernel<<<g, 128>>>(W16 + 344064, H1h, b2, O2, PRE, nullptr, 0);
    }
    bnstats_kernel<<<256, 256>>>(PRE, gamma, beta);
    bnapply_kernel<<<(589824 + 255) / 256, 256>>>(PRE, out);
}

// round 14
// speedup vs baseline: 1.0374x; 1.0374x over previous
#include <cuda_runtime.h>
#include <cuda_fp16.h>
#include <math.h>

#define NTOK 2304
#define HWDIM 48
#define FEATC 256
#define NKT 36
#define NQT 18

typedef unsigned long long ull;
typedef unsigned int u32;

__device__ float g_scratch[17763840];
__device__ float g_scale[256];
__device__ float g_shift[256];

__device__ __forceinline__ u32 f16pack(float lo, float hi) {
    u32 r;
    asm("cvt.rn.f16x2.f32 %0, %1, %2;" : "=r"(r) : "f"(hi), "f"(lo));
    return r;
}
__device__ __forceinline__ u32 ex2h2(u32 x) {
    u32 r;
    asm("ex2.approx.f16x2 %0, %1;" : "=r"(r) : "r"(x));
    return r;
}
__device__ __forceinline__ void mma16816(float* d, u32 a0, u32 a1, u32 a2, u32 a3,
                                         u32 b0, u32 b1) {
    asm volatile(
        "mma.sync.aligned.m16n8k16.row.col.f32.f16.f16.f32 "
        "{%0,%1,%2,%3},{%4,%5,%6,%7},{%8,%9},{%0,%1,%2,%3};"
        : "+f"(d[0]), "+f"(d[1]), "+f"(d[2]), "+f"(d[3])
        : "r"(a0), "r"(a1), "r"(a2), "r"(a3), "r"(b0), "r"(b1));
}
__device__ __forceinline__ u32 smem_u32(const void* p) {
    u32 a;
    asm("{ .reg .u64 t; cvta.to.shared.u64 t, %1; cvt.u32.u64 %0, t; }" : "=r"(a) : "l"(p));
    return a;
}
__device__ __forceinline__ void ldsm4(u32* r, u32 addr) {
    asm volatile("ldmatrix.sync.aligned.m8n8.x4.shared.b16 {%0,%1,%2,%3}, [%4];"
                 : "=r"(r[0]), "=r"(r[1]), "=r"(r[2]), "=r"(r[3]) : "r"(addr));
}
__device__ __forceinline__ void ldsm2(u32* r, u32 addr) {
    asm volatile("ldmatrix.sync.aligned.m8n8.x2.shared.b16 {%0,%1}, [%2];"
                 : "=r"(r[0]), "=r"(r[1]) : "r"(addr));
}
#define CP16(dst, src) asm volatile("cp.async.ca.shared.global [%0], [%1], 16;" :: "r"(dst), "l"(src))
#define CP_COMMIT()    asm volatile("cp.async.commit_group;" ::: "memory")
#define CP_WAIT0()     asm volatile("cp.async.wait_group 0;" ::: "memory")
#define CP_WAIT1()     asm volatile("cp.async.wait_group 1;" ::: "memory")

// ================= prep: weight conversion + PE channels (merged) =================
__global__ void prep_kernel(const float* __restrict__ wq, const float* __restrict__ wk,
                            const float* __restrict__ wv, const float* __restrict__ wfc,
                            const float* __restrict__ w1, const float* __restrict__ w2,
                            __half* __restrict__ W16, __half* __restrict__ XIN) {
    int idx = blockIdx.x * 256 + threadIdx.x;
    if (idx < 409600) {
        float v;
        if (idx < 147456) {
            int w = idx / 73728;
            int rem = idx - w * 73728;
            int r = rem / 288, c = rem - r * 288;
            const float* src = w ? wk : wq;
            v = (c < 286) ? src[(size_t)r * 286 + c] : 0.f;
        } else {
            int idx2 = idx - 147456;
            int w = idx2 >> 16, r = (idx2 >> 8) & 255, c = idx2 & 255;
            const float* src = (w == 0) ? wv : (w == 1) ? wfc : (w == 2) ? w1 : w2;
            v = src[(size_t)r * 256 + c];
        }
        W16[idx] = __float2half_rn(v);
    } else if (idx < 409600 + 32 * NTOK) {
        int idx2 = idx - 409600;
        int tok = idx2 >> 5, c = idx2 & 31;
        float val = 0.f;
        if (c < 30) {
            int i = tok / HWDIM, j = tok % HWDIM;
            const float SC = 6.283185307179586f;
            int axis = c / 10, t = c % 10;
            float e;
            if (axis == 0)      e = (float)(i + 1) / (HWDIM + 1e-6f) * SC;
            else if (axis == 1) e = (float)(j + 1) / (HWDIM + 1e-6f) * SC;
            else                e = SC;
            float freq = powf(10000.0f, (2.0f * (float)(t >> 1)) / 10.0f);
            float ph = e / freq;
            val = (t & 1) ? cosf(ph) : sinf(ph);
        }
        __half h = __float2half_rn(val);
#pragma unroll
        for (int s = 0; s < 8; s++)
            XIN[(size_t)s * 663552 + (size_t)tok * 288 + 256 + c] = h;
    }
}

// ================= input transpose+convert =================
__global__ void __launch_bounds__(256) xconv_kernel(const float* __restrict__ q,
                                                    const float* __restrict__ k,
                                                    const float* __restrict__ v,
                                                    __half* __restrict__ XIN) {
    __shared__ float tile[32][132];
    int z = blockIdx.z;
    int op = z >> 2, b = z & 3;
    const float* src = (op == 0 ? q : op == 1 ? k : v) + (size_t)b * FEATC * NTOK;
    int ldx = (op == 2) ? 256 : 288;
    __half* dst = XIN + (op == 2 ? (size_t)8 * 663552 + (size_t)b * 589824
                                 : (size_t)(op * 4 + b) * 663552);
    int t0 = blockIdx.x * 128, c0 = blockIdx.y * 32;
    int tid = threadIdx.x;
#pragma unroll
    for (int j = 0; j < 4; j++) {
        int i = tid + j * 256;
        int row = i >> 5, f4 = i & 31;
        float4 vv = *(const float4*)(src + (size_t)(c0 + row) * NTOK + t0 + f4 * 4);
        tile[row][f4 * 4] = vv.x;
        tile[row][f4 * 4 + 1] = vv.y;
        tile[row][f4 * 4 + 2] = vv.z;
        tile[row][f4 * 4 + 3] = vv.w;
    }
    __syncthreads();
#pragma unroll
    for (int j = 0; j < 2; j++) {
        int i = tid + j * 256;
        int tok = i >> 2, q4 = i & 3;
        u32 out4[4];
#pragma unroll
        for (int p = 0; p < 4; p++) {
            int c = q4 * 8 + p * 2;
            out4[p] = f16pack(tile[c][tok], tile[c + 1][tok]);
        }
        *(uint4*)(dst + (size_t)(t0 + tok) * ldx + c0 + q4 * 8) = *(uint4*)out4;
    }
}

// ================= HMMA GEMM body: 8 warps, 128x128, 3-stage cp.async, 1 sync/iter ==========
// stage i at i*20480: W tile (128 x 32, pitch 80), X tile at +10240 (128 x 32, pitch 80)
__device__ __forceinline__ void hgemm_body(const __half* __restrict__ W16, int kdim,
                                           const __half* __restrict__ XH, int ldx,
                                           const float* __restrict__ bVec,
                                           const float* __restrict__ resid,
                                           float qscale, int relu,
                                           float* __restrict__ outF,
                                           __half* __restrict__ outTok,
                                           __half* __restrict__ outC,
                                           unsigned char* smem) {
    int tid = threadIdx.x, wid = tid >> 5, lane = tid & 31;
    int wr = wid >> 2, wc = wid & 3;
    int oc0 = blockIdx.y * 128, t0 = blockIdx.x * 128;
    u32 sbase = smem_u32(smem);
    int nsteps = kdim >> 5;

    float acc[4][4][4];
#pragma unroll
    for (int m = 0; m < 4; m++)
#pragma unroll
        for (int n = 0; n < 4; n++)
#pragma unroll
            for (int c = 0; c < 4; c++) acc[m][n][c] = 0.f;

    // prologue: stages 0,1
#pragma unroll
    for (int ps = 0; ps < 2; ps++) {
        u32 sb = sbase + ps * 20480;
        int kk = ps << 5;
#pragma unroll
        for (int i = 0; i < 2; i++) {
            int idx = tid + i * 256;
            int row = idx >> 2, ch = idx & 3;
            CP16(sb + row * 80 + ch * 16, W16 + (size_t)(oc0 + row) * kdim + kk + ch * 8);
            CP16(sb + 10240 + row * 80 + ch * 16, XH + (size_t)(t0 + row) * ldx + kk + ch * 8);
        }
        CP_COMMIT();
    }

    for (int s = 0; s < nsteps; s++) {
        if (s == nsteps - 1) { CP_WAIT0(); } else { CP_WAIT1(); }
        __syncthreads();
        if (s + 2 < nsteps) {
            int kk = (s + 2) << 5;
            u32 sb = sbase + ((s + 2) % 3) * 20480;
#pragma unroll
            for (int i = 0; i < 2; i++) {
                int idx = tid + i * 256;
                int row = idx >> 2, ch = idx & 3;
                CP16(sb + row * 80 + ch * 16, W16 + (size_t)(oc0 + row) * kdim + kk + ch * 8);
                CP16(sb + 10240 + row * 80 + ch * 16, XH + (size_t)(t0 + row) * ldx + kk + ch * 8);
            }
            CP_COMMIT();
        }
        u32 sWst = sbase + (s % 3) * 20480;
        u32 sXst = sWst + 10240;
#pragma unroll
        for (int ks = 0; ks < 2; ks++) {
            int cb0 = ks * 16;
            u32 a[4][4], bfr[4][2];
#pragma unroll
            for (int m = 0; m < 4; m++) {
                int row = wr * 64 + m * 16 + (lane & 15);
                int col = cb0 + (lane >> 4) * 8;
                ldsm4(a[m], sWst + row * 80 + col * 2);
            }
#pragma unroll
            for (int p = 0; p < 2; p++) {
                u32 t[4];
                int row = wc * 32 + p * 16 + ((lane >> 4) & 1) * 8 + (lane & 7);
                int col = cb0 + ((lane >> 3) & 1) * 8;
                ldsm4(t, sXst + row * 80 + col * 2);
                bfr[2 * p][0] = t[0]; bfr[2 * p][1] = t[1];
                bfr[2 * p + 1][0] = t[2]; bfr[2 * p + 1][1] = t[3];
            }
#pragma unroll
            for (int m = 0; m < 4; m++)
#pragma unroll
                for (int n = 0; n < 4; n++)
                    mma16816(acc[m][n], a[m][0], a[m][1], a[m][2], a[m][3], bfr[n][0], bfr[n][1]);
        }
    }

#pragma unroll
    for (int m = 0; m < 4; m++) {
#pragma unroll
        for (int n = 0; n < 4; n++) {
            int r0 = oc0 + wr * 64 + m * 16 + (lane >> 2);
            int r1 = r0 + 8;
            int cX = t0 + wc * 32 + n * 8 + (lane & 3) * 2;
            float v00 = acc[m][n][0], v01 = acc[m][n][1];
            float v10 = acc[m][n][2], v11 = acc[m][n][3];
            if (bVec) {
                float bv0 = bVec[r0], bv1 = bVec[r1];
                v00 += bv0; v01 += bv0; v10 += bv1; v11 += bv1;
            }
            if (relu) {
                v00 = fmaxf(v00, 0.f); v01 = fmaxf(v01, 0.f);
                v10 = fmaxf(v10, 0.f); v11 = fmaxf(v11, 0.f);
            }
            if (resid) {
                v00 += resid[(size_t)r0 * NTOK + cX];
                v01 += resid[(size_t)r0 * NTOK + cX + 1];
                v10 += resid[(size_t)r1 * NTOK + cX];
                v11 += resid[(size_t)r1 * NTOK + cX + 1];
            }
            v00 *= qscale; v01 *= qscale; v10 *= qscale; v11 *= qscale;
            acc[m][n][0] = v00; acc[m][n][1] = v01; acc[m][n][2] = v10; acc[m][n][3] = v11;
            if (outF) {
                *(float2*)(outF + (size_t)r0 * NTOK + cX) = make_float2(v00, v01);
                *(float2*)(outF + (size_t)r1 * NTOK + cX) = make_float2(v10, v11);
            }
            if (outC) {
                *(u32*)(outC + (size_t)r0 * NTOK + cX) = f16pack(v00, v01);
                *(u32*)(outC + (size_t)r1 * NTOK + cX) = f16pack(v10, v11);
            }
        }
    }
    if (outTok) {
        __half (*sT)[136] = (__half(*)[136])smem;
        __syncthreads();
#pragma unroll
        for (int m = 0; m < 4; m++)
#pragma unroll
            for (int n = 0; n < 4; n++) {
                int lr0 = wr * 64 + m * 16 + (lane >> 2);
                int lc = wc * 32 + n * 8 + (lane & 3) * 2;
                sT[lc][lr0]     = __float2half_rn(acc[m][n][0]);
                sT[lc + 1][lr0] = __float2half_rn(acc[m][n][1]);
                sT[lc][lr0 + 8]     = __float2half_rn(acc[m][n][2]);
                sT[lc + 1][lr0 + 8] = __float2half_rn(acc[m][n][3]);
            }
        __syncthreads();
#pragma unroll
        for (int i = 0; i < 8; i++) {
            int idx = tid + i * 256;
            int row = idx >> 4, ch = idx & 15;
            *(uint4*)(outTok + (size_t)(t0 + row) * 256 + oc0 + ch * 8) =
                *(uint4*)&sT[row][ch * 8];
        }
    }
}

// proj: z = op*4 + b
__global__ void __launch_bounds__(256) proj_h_kernel(const __half* __restrict__ W16,
                                                     const __half* __restrict__ XIN,
                                                     __half* __restrict__ QH,
                                                     __half* __restrict__ KH,
                                                     __half* __restrict__ VH) {
    extern __shared__ __align__(16) unsigned char dynsmem[];
    int z = blockIdx.z;
    int op = z >> 2, b = z & 3;
    if (op == 0) {
        hgemm_body(W16, 288, XIN + (size_t)b * 663552, 288, nullptr, nullptr,
                   0.2550348634f, 0, nullptr, QH + (size_t)b * 589824, nullptr, dynsmem);
    } else if (op == 1) {
        hgemm_body(W16 + 73728, 288, XIN + (size_t)(4 + b) * 663552, 288, nullptr, nullptr,
                   1.0f, 0, nullptr, KH + (size_t)b * 589824, nullptr, dynsmem);
    } else {
        hgemm_body(W16 + 147456, 256, XIN + (size_t)8 * 663552 + (size_t)b * 589824, 256,
                   nullptr, nullptr, 1.0f, 0, nullptr, nullptr, VH + (size_t)b * 589824, dynsmem);
    }
}

__global__ void __launch_bounds__(256) hgemm_kernel(const __half* __restrict__ W16,
                                                    const __half* __restrict__ XH,
                                                    const float* __restrict__ bVec,
                                                    const float* __restrict__ resid,
                                                    float* __restrict__ outF,
                                                    __half* __restrict__ outTok,
                                                    int relu) {
    extern __shared__ __align__(16) unsigned char dynsmem[];
    size_t off = (size_t)blockIdx.z * 589824;
    hgemm_body(W16, 256, XH + off, 256, bVec, resid ? resid + off : nullptr, 1.0f, relu,
               outF ? outF + off : nullptr, outTok ? outTok + off : nullptr, nullptr, dynsmem);
}

// ================= warp-MMA flash attention: 3-stage cp.async, 1 sync/iter =================
// stage i: K (64x32, pitch 80) at sKV + i*10880 ; V (40x72, pitch 144) at +5120
__global__ void __launch_bounds__(128) attn_mma_kernel(const __half* __restrict__ QH,
                                                       const __half* __restrict__ KH,
                                                       const __half* __restrict__ VH,
                                                       __half* __restrict__ OH) {
    __shared__ __half sQ[128][40];
    __shared__ __align__(16) unsigned char sKV[32640];

    int tid = threadIdx.x, wid = tid >> 5, lane = tid & 31;
    int q0 = blockIdx.x * 128;
    int bh = blockIdx.y;
    int b = bh >> 3, h = bh & 7;
    u32 sQa = smem_u32(&sQ[0][0]);
    u32 sKVa = smem_u32(sKV);

#pragma unroll
    for (int c = 0; c < 4; c++) {
        int i = tid + c * 128;
        int row = i >> 2, ch = i & 3;
        *(uint4*)&sQ[row][ch * 8] =
            *(const uint4*)(QH + ((size_t)b * NTOK + q0 + row) * 256 + h * 32 + ch * 8);
    }
#pragma unroll
    for (int st = 0; st < 3; st++) {
        u32* v32 = (u32*)(sKV + st * 10880 + 5120 + 32 * 144);
        if (tid < 32) v32[tid] = 0x3C003C00u;
        u32* v33 = (u32*)(sKV + st * 10880 + 5120 + 33 * 144);
        for (int i = tid; i < 252; i += 128) v33[i] = 0u;
    }
#pragma unroll
    for (int ps = 0; ps < 2; ps++) {
        int kb = ps * 64;
        u32 sb = sKVa + ps * 10880;
#pragma unroll
        for (int i = 0; i < 2; i++) {
            int idx = tid + i * 128;
            int row = idx >> 2, ch = idx & 3;
            CP16(sb + row * 80 + ch * 16,
                 KH + ((size_t)b * NTOK + kb + row) * 256 + h * 32 + ch * 8);
        }
#pragma unroll
        for (int i = 0; i < 2; i++) {
            int idx = tid + i * 128;
            int row = idx >> 3, ch = idx & 7;
            CP16(sb + 5120 + row * 144 + ch * 16,
                 VH + ((size_t)(b * 256 + h * 32 + row)) * NTOK + kb + ch * 8);
        }
        CP_COMMIT();
    }
    __syncthreads();

    u32 qa[2][2][4];
#pragma unroll
    for (int m = 0; m < 2; m++)
#pragma unroll
        for (int ks = 0; ks < 2; ks++) {
            int row = wid * 32 + m * 16 + (lane & 15);
            int col = ks * 16 + (lane >> 4) * 8;
            ldsm4(qa[m][ks], sQa + row * 80 + col * 2);
        }

    float Oa[2][5][4];
#pragma unroll
    for (int m = 0; m < 2; m++)
#pragma unroll
        for (int n = 0; n < 5; n++)
#pragma unroll
            for (int c = 0; c < 4; c++) Oa[m][n][c] = 0.f;

#pragma unroll 1
    for (int kt = 0; kt < NKT; kt++) {
        if (kt == NKT - 1) { CP_WAIT0(); } else { CP_WAIT1(); }
        __syncthreads();
        if (kt + 2 < NKT) {
            int kb = (kt + 2) * 64;
            u32 sb = sKVa + ((kt + 2) % 3) * 10880;
#pragma unroll
            for (int i = 0; i < 2; i++) {
                int idx = tid + i * 128;
                int row = idx >> 2, ch = idx & 3;
                CP16(sb + row * 80 + ch * 16,
                     KH + ((size_t)b * NTOK + kb + row) * 256 + h * 32 + ch * 8);
            }
#pragma unroll
            for (int i = 0; i < 2; i++) {
                int idx = tid + i * 128;
                int row = idx >> 3, ch = idx & 7;
                CP16(sb + 5120 + row * 144 + ch * 16,
                     VH + ((size_t)(b * 256 + h * 32 + row)) * NTOK + kb + ch * 8);
            }
            CP_COMMIT();
        }
        u32 sKst = sKVa + (kt % 3) * 10880;
        u32 sVst = sKst + 5120;

        float S[2][8][4];
#pragma unroll
        for (int m = 0; m < 2; m++)
#pragma unroll
            for (int n = 0; n < 8; n++)
#pragma unroll
                for (int c = 0; c < 4; c++) S[m][n][c] = 0.f;

#pragma unroll
        for (int ks = 0; ks < 2; ks++) {
            int cb0 = ks * 16;
#pragma unroll
            for (int p = 0; p < 4; p++) {
                u32 t[4];
                int row = p * 16 + ((lane >> 4) & 1) * 8 + (lane & 7);
                int col = cb0 + ((lane >> 3) & 1) * 8;
                ldsm4(t, sKst + row * 80 + col * 2);
                mma16816(S[0][2 * p],     qa[0][ks][0], qa[0][ks][1], qa[0][ks][2], qa[0][ks][3], t[0], t[1]);
                mma16816(S[1][2 * p],     qa[1][ks][0], qa[1][ks][1], qa[1][ks][2], qa[1][ks][3], t[0], t[1]);
                mma16816(S[0][2 * p + 1], qa[0][ks][0], qa[0][ks][1], qa[0][ks][2], qa[0][ks][3], t[2], t[3]);
                mma16816(S[1][2 * p + 1], qa[1][ks][0], qa[1][ks][1], qa[1][ks][2], qa[1][ks][3], t[2], t[3]);
            }
        }

        u32 P[2][8][2];
#pragma unroll
        for (int m = 0; m < 2; m++)
#pragma unroll
            for (int nb = 0; nb < 8; nb++) {
                P[m][nb][0] = ex2h2(f16pack(S[m][nb][0], S[m][nb][1]));
                P[m][nb][1] = ex2h2(f16pack(S[m][nb][2], S[m][nb][3]));
            }

#pragma unroll
        for (int ks = 0; ks < 4; ks++) {
            int cb0 = ks * 16;
#pragma unroll
            for (int p = 0; p < 2; p++) {
                u32 t[4];
                int row = p * 16 + ((lane >> 4) & 1) * 8 + (lane & 7);
                int col = cb0 + ((lane >> 3) & 1) * 8;
                ldsm4(t, sVst + row * 144 + col * 2);
#pragma unroll
                for (int m = 0; m < 2; m++) {
                    mma16816(Oa[m][2 * p],     P[m][2 * ks][0], P[m][2 * ks][1],
                             P[m][2 * ks + 1][0], P[m][2 * ks + 1][1], t[0], t[1]);
                    mma16816(Oa[m][2 * p + 1], P[m][2 * ks][0], P[m][2 * ks][1],
                             P[m][2 * ks + 1][0], P[m][2 * ks + 1][1], t[2], t[3]);
                }
            }
            {
                u32 t2[2];
                int row = 32 + (lane & 7);
                int col = cb0 + ((lane >> 3) & 1) * 8;
                ldsm2(t2, sVst + row * 144 + col * 2);
#pragma unroll
                for (int m = 0; m < 2; m++)
                    mma16816(Oa[m][4], P[m][2 * ks][0], P[m][2 * ks][1],
                             P[m][2 * ks + 1][0], P[m][2 * ks + 1][1], t2[0], t2[1]);
            }
        }
    }

    int qb = q0 + wid * 32;
#pragma unroll
    for (int m = 0; m < 2; m++) {
        float li0 = 1.f / __shfl_sync(0xffffffffu, Oa[m][4][0], lane & ~3);
        float li1 = 1.f / __shfl_sync(0xffffffffu, Oa[m][4][2], lane & ~3);
        int r0 = qb + m * 16 + (lane >> 2);
#pragma unroll
        for (int nb = 0; nb < 4; nb++) {
            int d = nb * 8 + (lane & 3) * 2;
            *(u32*)(OH + ((size_t)b * NTOK + r0) * 256 + h * 32 + d) =
                f16pack(Oa[m][nb][0] * li0, Oa[m][nb][1] * li0);
            *(u32*)(OH + ((size_t)b * NTOK + r0 + 8) * 256 + h * 32 + d) =
                f16pack(Oa[m][nb][2] * li1, Oa[m][nb][3] * li1);
        }
    }
}

// ================= BN =================
__global__ void bnstats_kernel(const float* __restrict__ pre,
                               const float* __restrict__ gamma,
                               const float* __restrict__ beta) {
    int c = blockIdx.x;
    float s = 0.f, s2 = 0.f;
    for (int b = 0; b < 4; b++) {
        const float* p = pre + ((size_t)b * FEATC + c) * NTOK;
        for (int i = threadIdx.x; i < NTOK / 4; i += 256) {
            float4 v = ((const float4*)p)[i];
            s += v.x + v.y + v.z + v.w;
            s2 += v.x * v.x + v.y * v.y + v.z * v.z + v.w * v.w;
        }
    }
    __shared__ float sh0[256], sh1[256];
    sh0[threadIdx.x] = s;
    sh1[threadIdx.x] = s2;
    __syncthreads();
    for (int st = 128; st > 0; st >>= 1) {
        if (threadIdx.x < st) {
            sh0[threadIdx.x] += sh0[threadIdx.x + st];
            sh1[threadIdx.x] += sh1[threadIdx.x + st];
        }
        __syncthreads();
    }
    if (threadIdx.x == 0) {
        const float n = 4.0f * NTOK;
        float mean = sh0[0] / n;
        float var = sh1[0] / n - mean * mean;
        float is = rsqrtf(var + 1e-5f);
        float scl = gamma[c] * is;
        g_scale[c] = scl;
        g_shift[c] = beta[c] - mean * scl;
    }
}

__global__ void bnapply_kernel(const float* __restrict__ pre, float* __restrict__ out) {
    int idx = blockIdx.x * 256 + threadIdx.x;
    if (idx >= 589824) return;
    int c = ((idx << 2) / NTOK) & 255;
    float sc = g_scale[c], sh = g_shift[c];
    float4 v = ((const float4*)pre)[idx];
    v.x = v.x * sc + sh; v.y = v.y * sc + sh;
    v.z = v.z * sc + sh; v.w = v.w * sc + sh;
    ((float4*)out)[idx] = v;
}

// ================= launch =================
extern "C" void kernel_launch(void* const* d_in, const int* in_sizes, int n_in,
                              void* d_out, int out_size) {
    const float* q     = (const float*)d_in[0];
    const float* k     = (const float*)d_in[1];
    const float* v     = (const float*)d_in[2];
    const float* wq    = (const float*)d_in[3];
    const float* wk    = (const float*)d_in[4];
    const float* wv    = (const float*)d_in[5];
    const float* wfc   = (const float*)d_in[6];
    const float* w1    = (const float*)d_in[7];
    const float* b1    = (const float*)d_in[8];
    const float* w2    = (const float*)d_in[9];
    const float* b2    = (const float*)d_in[10];
    const float* gamma = (const float*)d_in[11];
    const float* beta  = (const float*)d_in[12];
    float* out = (float*)d_out;

    float* base = nullptr;
    cudaGetSymbolAddress((void**)&base, g_scratch);
    float* O2  = base;
    float* PRE = base + 2359296;
    __half* hb  = (__half*)(base + 4718592);
    __half* W16 = hb;
    __half* XIN = hb + 409600;
    __half* QH  = hb + 8077312;
    __half* KH  = QH + 2359296;
    __half* VH  = KH + 2359296;
    __half* OH  = VH + 2359296;
    __half* O2h = OH + 2359296;
    __half* H1h = O2h + 2359296;

    static bool attr_set = false;
    if (!attr_set) {
        cudaFuncSetAttribute(proj_h_kernel, cudaFuncAttributeMaxDynamicSharedMemorySize, 61440);
        cudaFuncSetAttribute(hgemm_kernel, cudaFuncAttributeMaxDynamicSharedMemorySize, 61440);
        attr_set = true;
    }

    prep_kernel<<<1888, 256>>>(wq, wk, wv, wfc, w1, w2, W16, XIN);
    {
        dim3 g(NTOK / 128, FEATC / 32, 12);
        xconv_kernel<<<g, 256>>>(q, k, v, XIN);
    }
    {
        dim3 g(NTOK / 128, 2, 12);
        proj_h_kernel<<<g, 256, 61440>>>(W16, XIN, QH, KH, VH);
    }
    {
        dim3 ga(NQT, 32);
        attn_mma_kernel<<<ga, 128>>>(QH, KH, VH, OH);
    }
    {
        dim3 g(NTOK / 128, 2, 4);
        hgemm_kernel<<<g, 256, 61440>>>(W16 + 212992, OH, nullptr, nullptr, O2, O2h, 0);
        hgemm_kernel<<<g, 256, 61440>>>(W16 + 278528, O2h, b1, nullptr, nullptr, H1h, 1);
        hgemm_kernel<<<g, 256, 61440>>>(W16 + 344064, H1h, b2, O2, PRE, nullptr, 0);
    }
    bnstats_kernel<<<256, 256>>>(PRE, gamma, beta);
    bnapply_kernel<<<(589824 + 255) / 256, 256>>>(PRE, out);
}